// round 8
// baseline (speedup 1.0000x reference)
#include <cuda_runtime.h>

// 3D neighborhood attention, B=2, H=W=T=64, C=96, NH=6, HD=16, KS=3 (27 window).
// Smem-tiled: block = 1h x 2w x 32t positions, 3 heads (channel-split).
// k tile (3x4x34 rows x 48ch, zero-padded halo) + scaled q tile staged in smem.
// Thread = one (pos, head): 27 full 16-wide dots via conflict-free LDS.128,
// all offsets compile-time. No shuffles, no predicates in the hot loop.
// Grid = 2(g) x 2(b) x 64(h) x 32(wt) x 2(tt) = 16384, block = 192, 2 blocks/SM.

#define KROW 52                      // padded row stride (floats); 52%8==4 -> conflict-free
#define K_FLOATS (12 * 34 * KROW)    // 21216
#define Q_FLOATS (64 * KROW)         // 3328

__global__ void __launch_bounds__(192, 2)
natt3d_smem(const float* __restrict__ q, const float* __restrict__ k,
            const float* __restrict__ rpb, float* __restrict__ out) {
    extern __shared__ float smem[];
    float* ks = smem;
    float* qs = smem + K_FLOATS;
    float* rs = qs + Q_FLOATS;

    const int tid = threadIdx.x;
    const int bx  = blockIdx.x;
    const int tt  = bx & 1;
    const int wt  = (bx >> 1) & 31;
    const int h0  = (bx >> 6) & 63;
    const int b   = (bx >> 12) & 1;
    const int g   = bx >> 13;              // head group: heads g*3..g*3+2
    const int w0  = wt * 2;
    const int t0  = tt * 32;
    const int cg  = g * 48;

    if (tid < 81) rs[tid] = rpb[g * 81 + tid];

    const long bbase = (long)b * (64L * 64 * 64 * 96);

    // ---- fill k tile: 3(dh) x 4(dw) x 34(dt) x 12(float4) slots, zero halo ----
    for (int idx = tid; idx < 4896; idx += 192) {
        const int c4 = idx % 12;
        const int r  = idx / 12;
        const int dt = r % 34;
        const int rr = r / 34;             // dh*4 + dw
        const int ww = w0 - 1 + (rr & 3);
        const int hh = h0 - 1 + (rr >> 2);
        const int t  = t0 - 1 + dt;
        float4 v = make_float4(0.f, 0.f, 0.f, 0.f);
        if ((unsigned)hh < 64u && (unsigned)ww < 64u && (unsigned)t < 64u) {
            v = *reinterpret_cast<const float4*>(
                k + bbase + (((long)hh * 64 + ww) * 64 + t) * 96 + cg + c4 * 4);
        }
        *reinterpret_cast<float4*>(ks + r * KROW + c4 * 4) = v;
    }

    // ---- fill q tile (pre-scaled by HD^-0.5 = 0.25): 2(w) x 32(t) x 12 slots ----
    for (int idx = tid; idx < 768; idx += 192) {
        const int c4 = idx % 12;
        const int r  = idx / 12;           // wl*32 + tl
        const int tl = r & 31;
        const int wl = r >> 5;
        float4 v = *reinterpret_cast<const float4*>(
            q + bbase + (((long)h0 * 64 + w0 + wl) * 64 + t0 + tl) * 96 + cg + c4 * 4);
        v.x *= 0.25f; v.y *= 0.25f; v.z *= 0.25f; v.w *= 0.25f;
        *reinterpret_cast<float4*>(qs + r * KROW + c4 * 4) = v;
    }
    __syncthreads();

    // ---- compute: warp = (head_local x w_local), lane = t_local ----
    const int lane = tid & 31;
    const int warp = tid >> 5;             // 0..5
    const int wl   = warp & 1;
    const int hl   = warp >> 1;            // head_local 0..2

    const float* qrow = qs + (wl * 32 + lane) * KROW + hl * 16;
    const float4 q0 = *(const float4*)(qrow + 0);
    const float4 q1 = *(const float4*)(qrow + 4);
    const float4 q2 = *(const float4*)(qrow + 8);
    const float4 q3 = *(const float4*)(qrow + 12);

    const float* kbase = ks + (wl * 34 + lane) * KROW + hl * 16;
    const float* rb    = rs + hl * 27;

    float sum = 0.f, ax = 0.f, ay = 0.f, az = 0.f;

    #pragma unroll
    for (int n = 0; n < 27; ++n) {
        const int i = n / 9, j = (n / 3) % 3, l = n % 3;   // compile-time
        const float* kp = kbase + ((i * 4 + j) * 34 + l) * KROW;
        const float4 k0 = *(const float4*)(kp + 0);
        const float4 k1 = *(const float4*)(kp + 4);
        const float4 k2 = *(const float4*)(kp + 8);
        const float4 k3 = *(const float4*)(kp + 12);
        float d = q0.x * k0.x;
        d = fmaf(q0.y, k0.y, d); d = fmaf(q0.z, k0.z, d); d = fmaf(q0.w, k0.w, d);
        d = fmaf(q1.x, k1.x, d); d = fmaf(q1.y, k1.y, d);
        d = fmaf(q1.z, k1.z, d); d = fmaf(q1.w, k1.w, d);
        d = fmaf(q2.x, k2.x, d); d = fmaf(q2.y, k2.y, d);
        d = fmaf(q2.z, k2.z, d); d = fmaf(q2.w, k2.w, d);
        d = fmaf(q3.x, k3.x, d); d = fmaf(q3.y, k3.y, d);
        d = fmaf(q3.z, k3.z, d); d = fmaf(q3.w, k3.w, d);
        const float e = __expf(d + rb[n]);
        sum += e;
        ax = fmaf(e, (float)(i - 1), ax);
        ay = fmaf(e, (float)(j - 1), ay);
        az = fmaf(e, (float)(l - 1), az);
    }

    const float inv = __fdividef(1.0f, sum);
    const int head = g * 3 + hl;
    // out[b][head*3+comp][h][w][t], plane stride 64^3
    long obase = ((((long)b * 18 + head * 3) * 64 + h0) * 64 + (w0 + wl)) * 64
               + t0 + lane;
    out[obase]              = ax * inv;
    out[obase + 262144]     = ay * inv;
    out[obase + 2 * 262144] = az * inv;
}

extern "C" void kernel_launch(void* const* d_in, const int* in_sizes, int n_in,
                              void* d_out, int out_size) {
    const float* q   = (const float*)d_in[0];
    const float* k   = (const float*)d_in[1];
    const float* rpb = (const float*)d_in[2];
    float* out = (float*)d_out;

    const int smem_bytes = (K_FLOATS + Q_FLOATS + 96) * sizeof(float);  // ~98.6KB
    cudaFuncSetAttribute(natt3d_smem,
                         cudaFuncAttributeMaxDynamicSharedMemorySize, smem_bytes);
    natt3d_smem<<<16384, 192, smem_bytes>>>(q, k, rpb, out);
}

// round 12
// speedup vs baseline: 1.0861x; 1.0861x over previous
#include <cuda_runtime.h>

// 3D neighborhood attention, B=2, H=W=T=64, C=96, NH=6, HD=16, KS=3 (27 window).
// Smem-tiled: block = 2h x 4w x 32t positions, 3 heads (channel-split per block).
// k tile 4x6x34 rows x 48ch (zero halo) + scaled q tile in smem (~218KB), 768 thr,
// 1 block/SM = 24 warps. Thread = one (pos, head): 27 full 16-wide dots via
// conflict-free LDS.128 (KROW=52 -> 8-lane phases tile all 32 banks), all window
// offsets compile-time. Grid = 2(g) x 2(b) x 32(ht) x 16(wt) x 2(tt) = 4096.
// [R11 infra-failed; identical logic resubmitted.]

#define KROW 52
#define K_ROWS (4 * 6 * 34)           // 816
#define K_FLOATS (K_ROWS * KROW)      // 42432
#define Q_FLOATS (256 * KROW)         // 13312

__global__ void __launch_bounds__(768, 1)
natt3d_smem2(const float* __restrict__ q, const float* __restrict__ k,
             const float* __restrict__ rpb, float* __restrict__ out) {
    extern __shared__ float smem[];
    float* ks = smem;
    float* qs = smem + K_FLOATS;
    float* rs = qs + Q_FLOATS;

    const int tid = threadIdx.x;
    const int bx  = blockIdx.x;
    const int tt  = bx & 1;
    const int wt  = (bx >> 1) & 15;
    const int ht  = (bx >> 5) & 31;
    const int b   = (bx >> 10) & 1;
    const int g   = bx >> 11;             // head group: heads g*3..g*3+2
    const int w0  = wt * 4;
    const int h0  = ht * 2;
    const int t0  = tt * 32;
    const int cg  = g * 48;

    if (tid < 81) rs[tid] = __ldg(rpb + g * 81 + tid);

    const long bbase = (long)b * (64L * 64 * 64 * 96);

    // ---- fill k tile: 4(dh) x 6(dw) x 34(dt) rows x 12 float4, zero halo ----
    #pragma unroll
    for (int pass = 0; pass < 13; ++pass) {
        const int idx = pass * 768 + tid;         // 9792 slots total
        if (idx < 9792) {
            const int c4 = idx % 12;
            const int r  = idx / 12;
            const int dt = r % 34;
            const int rr = r / 34;                // dh*6 + dw
            const int ww = w0 - 1 + (rr % 6);
            const int hh = h0 - 1 + (rr / 6);
            const int t  = t0 - 1 + dt;
            float4 v = make_float4(0.f, 0.f, 0.f, 0.f);
            if ((unsigned)hh < 64u && (unsigned)ww < 64u && (unsigned)t < 64u) {
                v = *reinterpret_cast<const float4*>(
                    k + bbase + (((long)hh * 64 + ww) * 64 + t) * 96 + cg + c4 * 4);
            }
            *reinterpret_cast<float4*>(ks + r * KROW + c4 * 4) = v;
        }
    }

    // ---- fill q tile (pre-scaled by 0.25): 2h x 4w x 32t rows x 12 float4 ----
    #pragma unroll
    for (int pass = 0; pass < 4; ++pass) {
        const int idx = pass * 768 + tid;         // 3072 slots
        const int c4 = idx % 12;
        const int r  = idx / 12;                  // (hh*4+ww)*32 + tl
        const int tl = r & 31;
        const int ww = (r >> 5) & 3;
        const int hh = r >> 7;
        float4 v = *reinterpret_cast<const float4*>(
            q + bbase + (((long)(h0 + hh) * 64 + w0 + ww) * 64 + t0 + tl) * 96
              + cg + c4 * 4);
        v.x *= 0.25f; v.y *= 0.25f; v.z *= 0.25f; v.w *= 0.25f;
        *reinterpret_cast<float4*>(qs + r * KROW + c4 * 4) = v;
    }
    __syncthreads();

    // ---- compute: warp = (head_local(3) x hh(2) x ww(4)), lane = t ----
    const int lane = tid & 31;
    const int warp = tid >> 5;            // 0..23
    const int hl   = warp >> 3;           // head_local 0..2
    const int wp   = warp & 7;
    const int hhl  = wp >> 2;             // 0..1
    const int wwl  = wp & 3;              // 0..3

    const float* qrow = qs + ((hhl * 4 + wwl) * 32 + lane) * KROW + hl * 16;
    const float4 q0 = *(const float4*)(qrow + 0);
    const float4 q1 = *(const float4*)(qrow + 4);
    const float4 q2 = *(const float4*)(qrow + 8);
    const float4 q3 = *(const float4*)(qrow + 12);

    const float* kbase = ks + ((hhl * 6 + wwl) * 34 + lane) * KROW + hl * 16;
    const float* rb    = rs + hl * 27;

    float sum = 0.f, ax = 0.f, ay = 0.f, az = 0.f;

    #pragma unroll
    for (int cidx = 0; cidx < 9; ++cidx) {        // (i,j) column, compile-time
        const int i = cidx / 3, j = cidx % 3;
        const float* cp = kbase + ((i * 6 + j) * 34) * KROW;
        #pragma unroll
        for (int l = 0; l < 3; ++l) {
            const float* kp = cp + l * KROW;
            const float4 k0 = *(const float4*)(kp + 0);
            const float4 k1 = *(const float4*)(kp + 4);
            const float4 k2 = *(const float4*)(kp + 8);
            const float4 k3 = *(const float4*)(kp + 12);
            float d = q0.x * k0.x;
            d = fmaf(q0.y, k0.y, d); d = fmaf(q0.z, k0.z, d); d = fmaf(q0.w, k0.w, d);
            d = fmaf(q1.x, k1.x, d); d = fmaf(q1.y, k1.y, d);
            d = fmaf(q1.z, k1.z, d); d = fmaf(q1.w, k1.w, d);
            d = fmaf(q2.x, k2.x, d); d = fmaf(q2.y, k2.y, d);
            d = fmaf(q2.z, k2.z, d); d = fmaf(q2.w, k2.w, d);
            d = fmaf(q3.x, k3.x, d); d = fmaf(q3.y, k3.y, d);
            d = fmaf(q3.w, k3.w, fmaf(q3.z, k3.z, d));
            const float e = __expf(d + rb[cidx * 3 + l]);
            sum += e;
            ax = fmaf(e, (float)(i - 1), ax);
            ay = fmaf(e, (float)(j - 1), ay);
            az = fmaf(e, (float)(l - 1), az);
        }
    }

    const float inv = __fdividef(1.0f, sum);
    const int head = g * 3 + hl;
    // out[b][head*3+comp][h][w][t], plane stride 64^3; lanes = consecutive t
    long obase = ((((long)b * 18 + head * 3) * 64 + (h0 + hhl)) * 64 + (w0 + wwl)) * 64
               + t0 + lane;
    out[obase]              = ax * inv;
    out[obase + 262144]     = ay * inv;
    out[obase + 2 * 262144] = az * inv;
}

extern "C" void kernel_launch(void* const* d_in, const int* in_sizes, int n_in,
                              void* d_out, int out_size) {
    const float* q   = (const float*)d_in[0];
    const float* k   = (const float*)d_in[1];
    const float* rpb = (const float*)d_in[2];
    float* out = (float*)d_out;

    const int smem_bytes = (K_FLOATS + Q_FLOATS + 96) * sizeof(float); // 223360 B
    cudaFuncSetAttribute(natt3d_smem2,
                         cudaFuncAttributeMaxDynamicSharedMemorySize, smem_bytes);
    natt3d_smem2<<<4096, 768, smem_bytes>>>(q, k, rpb, out);
}

// round 13
// speedup vs baseline: 1.7496x; 1.6109x over previous
#include <cuda_runtime.h>

// 3D neighborhood attention, B=2, H=W=T=64, C=96, NH=6, HD=16, KS=3 (27 window).
// Block = 2h x 4w x 32t positions, 3 heads (channel-split), 768 thr, ~218KB smem.
// NEW vs R12: warp-level k reuse along t. Each lane loads only its OWN k row per
// (i,j) column and computes dots vs q[t-1],q[t],q[t+1]; off-diagonal scores are
// exchanged with shfl up/down. Edge lanes (0,31) compute halo dots themselves.
// k LDS per thread: 108 -> ~36.

#define KROW 52                       // conflict-free: 8-lane phases tile 32 banks
#define K_ROWS (4 * 6 * 34)           // 816
#define K_FLOATS (K_ROWS * KROW)      // 42432
#define Q_FLOATS (256 * KROW)         // 13312

__global__ void __launch_bounds__(768, 1)
natt3d_shfl(const float* __restrict__ q, const float* __restrict__ k,
            const float* __restrict__ rpb, float* __restrict__ out) {
    extern __shared__ float smem[];
    float* ks = smem;
    float* qs = smem + K_FLOATS;
    float* rs = qs + Q_FLOATS;

    const int tid = threadIdx.x;
    const int bx  = blockIdx.x;
    const int tt  = bx & 1;
    const int wt  = (bx >> 1) & 15;
    const int ht  = (bx >> 5) & 31;
    const int b   = (bx >> 10) & 1;
    const int g   = bx >> 11;             // head group: heads g*3..g*3+2
    const int w0  = wt * 4;
    const int h0  = ht * 2;
    const int t0  = tt * 32;
    const int cg  = g * 48;

    if (tid < 81) rs[tid] = __ldg(rpb + g * 81 + tid);

    const long bbase = (long)b * (64L * 64 * 64 * 96);

    // ---- fill k tile: 4(dh) x 6(dw) x 34(dt) rows x 12 float4, zero halo ----
    #pragma unroll
    for (int pass = 0; pass < 13; ++pass) {
        const int idx = pass * 768 + tid;         // 9792 slots
        if (idx < 9792) {
            const int c4 = idx % 12;
            const int r  = idx / 12;
            const int dt = r % 34;
            const int rr = r / 34;                // dh*6 + dw
            const int ww = w0 - 1 + (rr % 6);
            const int hh = h0 - 1 + (rr / 6);
            const int t  = t0 - 1 + dt;
            float4 v = make_float4(0.f, 0.f, 0.f, 0.f);
            if ((unsigned)hh < 64u && (unsigned)ww < 64u && (unsigned)t < 64u) {
                v = *reinterpret_cast<const float4*>(
                    k + bbase + (((long)hh * 64 + ww) * 64 + t) * 96 + cg + c4 * 4);
            }
            *reinterpret_cast<float4*>(ks + r * KROW + c4 * 4) = v;
        }
    }

    // ---- fill q tile (pre-scaled by 0.25): 2h x 4w x 32t rows x 12 float4 ----
    #pragma unroll
    for (int pass = 0; pass < 4; ++pass) {
        const int idx = pass * 768 + tid;         // 3072 slots
        const int c4 = idx % 12;
        const int r  = idx / 12;                  // (hh*4+ww)*32 + tl
        const int tl = r & 31;
        const int ww = (r >> 5) & 3;
        const int hh = r >> 7;
        float4 v = *reinterpret_cast<const float4*>(
            q + bbase + (((long)(h0 + hh) * 64 + w0 + ww) * 64 + t0 + tl) * 96
              + cg + c4 * 4);
        v.x *= 0.25f; v.y *= 0.25f; v.z *= 0.25f; v.w *= 0.25f;
        *reinterpret_cast<float4*>(qs + r * KROW + c4 * 4) = v;
    }
    __syncthreads();

    // ---- compute: warp = (head_local(3) x hh(2) x ww(4)), lane = t ----
    const int lane = tid & 31;
    const int warp = tid >> 5;            // 0..23
    const int hl   = warp >> 3;           // head_local 0..2
    const int wp   = warp & 7;
    const int hhl  = wp >> 2;
    const int wwl  = wp & 3;

    const int prow = (hhl * 4 + wwl) * 32 + lane;
    const float* q0p = qs + prow * KROW + hl * 16;
    // q[t], q[t-1], q[t+1]. For lane 0 the "t-1" vector and for lane 31 the
    // "t+1" vector read adjacent (wrong-position but valid) smem; the dot
    // products built from them are provably discarded (shuffled off-warp or
    // overridden by the edge dot), so the values never reach an output.
    const float4 q0a = *(const float4*)(q0p + 0),  q0b = *(const float4*)(q0p + 4);
    const float4 q0c = *(const float4*)(q0p + 8),  q0d = *(const float4*)(q0p + 12);
    const float4 qma = *(const float4*)(q0p - KROW + 0),  qmb = *(const float4*)(q0p - KROW + 4);
    const float4 qmc = *(const float4*)(q0p - KROW + 8),  qmd = *(const float4*)(q0p - KROW + 12);
    const float4 qpa = *(const float4*)(q0p + KROW + 0),  qpb = *(const float4*)(q0p + KROW + 4);
    const float4 qpc = *(const float4*)(q0p + KROW + 8),  qpd = *(const float4*)(q0p + KROW + 12);

    const float* kcol0 = ks + ((hhl * 6 + wwl) * 34) * KROW + hl * 16;
    const float* rb    = rs + hl * 27;
    const bool  is_e0  = (lane == 0);
    const bool  is_e31 = (lane == 31);
    const int   erow   = is_e0 ? 0 : 33;       // halo row index for edge dot

    float sum = 0.f, ax = 0.f, ay = 0.f, az = 0.f;

    #pragma unroll
    for (int cidx = 0; cidx < 9; ++cidx) {         // (i,j) column, compile-time
        const int i = cidx / 3, j = cidx % 3;
        const float* cb = kcol0 + ((i * 6 + j) * 34) * KROW;
        const float* kp = cb + (lane + 1) * KROW;  // own t row
        const float4 k0 = *(const float4*)(kp + 0);
        const float4 k1 = *(const float4*)(kp + 4);
        const float4 k2 = *(const float4*)(kp + 8);
        const float4 k3 = *(const float4*)(kp + 12);

        // pB = dot(q[t],  k[t])   -> own l=0
        float b0 = q0a.x*k0.x, b1 = q0a.y*k0.y;
        b0 = fmaf(q0a.z,k0.z,b0); b1 = fmaf(q0a.w,k0.w,b1);
        b0 = fmaf(q0b.x,k1.x,b0); b1 = fmaf(q0b.y,k1.y,b1);
        b0 = fmaf(q0b.z,k1.z,b0); b1 = fmaf(q0b.w,k1.w,b1);
        b0 = fmaf(q0c.x,k2.x,b0); b1 = fmaf(q0c.y,k2.y,b1);
        b0 = fmaf(q0c.z,k2.z,b0); b1 = fmaf(q0c.w,k2.w,b1);
        b0 = fmaf(q0d.x,k3.x,b0); b1 = fmaf(q0d.y,k3.y,b1);
        b0 = fmaf(q0d.z,k3.z,b0); b1 = fmaf(q0d.w,k3.w,b1);
        const float pB = b0 + b1;

        // pA = dot(q[t-1], k[t])  -> neighbor (t-1)'s l=+1
        float a0 = qma.x*k0.x, a1 = qma.y*k0.y;
        a0 = fmaf(qma.z,k0.z,a0); a1 = fmaf(qma.w,k0.w,a1);
        a0 = fmaf(qmb.x,k1.x,a0); a1 = fmaf(qmb.y,k1.y,a1);
        a0 = fmaf(qmb.z,k1.z,a0); a1 = fmaf(qmb.w,k1.w,a1);
        a0 = fmaf(qmc.x,k2.x,a0); a1 = fmaf(qmc.y,k2.y,a1);
        a0 = fmaf(qmc.z,k2.z,a0); a1 = fmaf(qmc.w,k2.w,a1);
        a0 = fmaf(qmd.x,k3.x,a0); a1 = fmaf(qmd.y,k3.y,a1);
        a0 = fmaf(qmd.z,k3.z,a0); a1 = fmaf(qmd.w,k3.w,a1);
        const float pA = a0 + a1;

        // pC = dot(q[t+1], k[t])  -> neighbor (t+1)'s l=-1
        float c0 = qpa.x*k0.x, c1 = qpa.y*k0.y;
        c0 = fmaf(qpa.z,k0.z,c0); c1 = fmaf(qpa.w,k0.w,c1);
        c0 = fmaf(qpb.x,k1.x,c0); c1 = fmaf(qpb.y,k1.y,c1);
        c0 = fmaf(qpb.z,k1.z,c0); c1 = fmaf(qpb.w,k1.w,c1);
        c0 = fmaf(qpc.x,k2.x,c0); c1 = fmaf(qpc.y,k2.y,c1);
        c0 = fmaf(qpc.z,k2.z,c0); c1 = fmaf(qpc.w,k2.w,c1);
        c0 = fmaf(qpd.x,k3.x,c0); c1 = fmaf(qpd.y,k3.y,c1);
        c0 = fmaf(qpd.z,k3.z,c0); c1 = fmaf(qpd.w,k3.w,c1);
        const float pC = c0 + c1;

        // edge lanes: missing halo dot, uses own q[t] against halo k row
        float pE = 0.f;
        if (is_e0 || is_e31) {
            const float* ke = cb + erow * KROW;
            const float4 e0 = *(const float4*)(ke + 0);
            const float4 e1 = *(const float4*)(ke + 4);
            const float4 e2 = *(const float4*)(ke + 8);
            const float4 e3 = *(const float4*)(ke + 12);
            float x0 = q0a.x*e0.x, x1 = q0a.y*e0.y;
            x0 = fmaf(q0a.z,e0.z,x0); x1 = fmaf(q0a.w,e0.w,x1);
            x0 = fmaf(q0b.x,e1.x,x0); x1 = fmaf(q0b.y,e1.y,x1);
            x0 = fmaf(q0b.z,e1.z,x0); x1 = fmaf(q0b.w,e1.w,x1);
            x0 = fmaf(q0c.x,e2.x,x0); x1 = fmaf(q0c.y,e2.y,x1);
            x0 = fmaf(q0c.z,e2.z,x0); x1 = fmaf(q0c.w,e2.w,x1);
            x0 = fmaf(q0d.x,e3.x,x0); x1 = fmaf(q0d.y,e3.y,x1);
            x0 = fmaf(q0d.z,e3.z,x0); x1 = fmaf(q0d.w,e3.w,x1);
            pE = x0 + x1;
        }

        float s_up = __shfl_down_sync(0xffffffffu, pA, 1);  // = dot(q[t], k[t+1])
        float s_dn = __shfl_up_sync  (0xffffffffu, pC, 1);  // = dot(q[t], k[t-1])
        if (is_e0)  s_dn = pE;
        if (is_e31) s_up = pE;

        const float e_dn = __expf(s_dn + rb[cidx * 3 + 0]);
        const float e_0  = __expf(pB   + rb[cidx * 3 + 1]);
        const float e_up = __expf(s_up + rb[cidx * 3 + 2]);
        const float es   = e_dn + e_0 + e_up;
        sum += es;
        if (i == 0) ax -= es; else if (i == 2) ax += es;
        if (j == 0) ay -= es; else if (j == 2) ay += es;
        az += e_up - e_dn;
    }

    const float inv = __fdividef(1.0f, sum);
    const int head = g * 3 + hl;
    long obase = ((((long)b * 18 + head * 3) * 64 + (h0 + hhl)) * 64 + (w0 + wwl)) * 64
               + t0 + lane;
    out[obase]              = ax * inv;
    out[obase + 262144]     = ay * inv;
    out[obase + 2 * 262144] = az * inv;
}

extern "C" void kernel_launch(void* const* d_in, const int* in_sizes, int n_in,
                              void* d_out, int out_size) {
    const float* q   = (const float*)d_in[0];
    const float* k   = (const float*)d_in[1];
    const float* rpb = (const float*)d_in[2];
    float* out = (float*)d_out;

    const int smem_bytes = (K_FLOATS + Q_FLOATS + 96) * sizeof(float); // 223360 B
    cudaFuncSetAttribute(natt3d_shfl,
                         cudaFuncAttributeMaxDynamicSharedMemorySize, smem_bytes);
    natt3d_shfl<<<4096, 768, smem_bytes>>>(q, k, rpb, out);
}

// round 15
// speedup vs baseline: 1.7635x; 1.0080x over previous
#include <cuda_runtime.h>

// 3D neighborhood attention, B=2, H=W=T=64, C=96, NH=6, HD=16, KS=3 (27 window).
// Block = 2h x 4w x 32t positions, 3 heads (channel-split), 768 thr, ~218KB smem.
// R13 structure (warp shuffle k-reuse along t) + NEW: all dot products via
// packed fma.rn.f32x2 (FFMA2) on ulonglong2 smem loads -> no pack movs,
// ~25% fewer issued instructions. Fill loops use hoisted index decomposition.

#define KROW 52
#define K_ROWS (4 * 6 * 34)           // 816
#define K_FLOATS (K_ROWS * KROW)      // 42432
#define Q_FLOATS (256 * KROW)         // 13312

typedef unsigned long long ull;

__device__ __forceinline__ ull mul2(ull a, ull b) {
    ull d; asm("mul.rn.f32x2 %0, %1, %2;" : "=l"(d) : "l"(a), "l"(b)); return d;
}
__device__ __forceinline__ ull ffma2(ull a, ull b, ull c) {
    ull d; asm("fma.rn.f32x2 %0, %1, %2, %3;" : "=l"(d) : "l"(a), "l"(b), "l"(c));
    return d;
}
__device__ __forceinline__ float hadd2(ull v) {
    float lo, hi;
    asm("mov.b64 {%0,%1}, %2;" : "=f"(lo), "=f"(hi) : "l"(v));
    return lo + hi;
}
// packed dot of 8 f32x2 pairs: 1 mul2 + 7 ffma2
__device__ __forceinline__ float dot16(const ull* a, const ull* b) {
    ull acc = mul2(a[0], b[0]);
    acc = ffma2(a[1], b[1], acc); acc = ffma2(a[2], b[2], acc);
    acc = ffma2(a[3], b[3], acc); acc = ffma2(a[4], b[4], acc);
    acc = ffma2(a[5], b[5], acc); acc = ffma2(a[6], b[6], acc);
    acc = ffma2(a[7], b[7], acc);
    return hadd2(acc);
}
__device__ __forceinline__ void load8(ull* r, const float* p) {
    const ulonglong2* v = (const ulonglong2*)p;
    ulonglong2 v0 = v[0], v1 = v[1], v2 = v[2], v3 = v[3];
    r[0] = v0.x; r[1] = v0.y; r[2] = v1.x; r[3] = v1.y;
    r[4] = v2.x; r[5] = v2.y; r[6] = v3.x; r[7] = v3.y;
}

__global__ void __launch_bounds__(768, 1)
natt3d_f32x2(const float* __restrict__ q, const float* __restrict__ k,
             const float* __restrict__ rpb, float* __restrict__ out) {
    extern __shared__ float smem[];
    float* ks = smem;
    float* qs = smem + K_FLOATS;
    float* rs = qs + Q_FLOATS;

    const int tid = threadIdx.x;
    const int bx  = blockIdx.x;
    const int tt  = bx & 1;
    const int wt  = (bx >> 1) & 15;
    const int ht  = (bx >> 5) & 31;
    const int b   = (bx >> 10) & 1;
    const int g   = bx >> 11;             // head group: heads g*3..g*3+2
    const int w0  = wt * 4;
    const int h0  = ht * 2;
    const int t0  = tt * 32;
    const int cg  = g * 48;

    if (tid < 81) rs[tid] = __ldg(rpb + g * 81 + tid);

    const long bbase = (long)b * (64L * 64 * 64 * 96);

    // ---- fill k tile: 816 rows (4dh x 6dw x 34dt) x 12 float4, zero halo ----
    {
        const int c4 = tid % 12;          // hoisted: constant across passes
        int r = tid / 12;                 // 64 rows per pass
        #pragma unroll
        for (int pass = 0; pass < 13; ++pass, r += 64) {
            if (r < 816) {
                const int dt = r % 34;
                const int rr = r / 34;            // dh*6 + dw
                const int ww = w0 - 1 + (rr % 6);
                const int hh = h0 - 1 + (rr / 6);
                const int t  = t0 - 1 + dt;
                float4 v = make_float4(0.f, 0.f, 0.f, 0.f);
                if ((unsigned)hh < 64u && (unsigned)ww < 64u && (unsigned)t < 64u) {
                    v = *reinterpret_cast<const float4*>(
                        k + bbase + (((long)hh * 64 + ww) * 64 + t) * 96 + cg + c4 * 4);
                }
                *reinterpret_cast<float4*>(ks + r * KROW + c4 * 4) = v;
            }
        }
    }

    // ---- fill q tile (pre-scaled by 0.25): 256 rows x 12 float4 ----
    {
        const int c4 = tid % 12;
        int r = tid / 12;
        #pragma unroll
        for (int pass = 0; pass < 4; ++pass, r += 64) {
            const int tl = r & 31;
            const int ww = (r >> 5) & 3;
            const int hh = r >> 7;
            float4 v = *reinterpret_cast<const float4*>(
                q + bbase + (((long)(h0 + hh) * 64 + w0 + ww) * 64 + t0 + tl) * 96
                  + cg + c4 * 4);
            v.x *= 0.25f; v.y *= 0.25f; v.z *= 0.25f; v.w *= 0.25f;
            *reinterpret_cast<float4*>(qs + r * KROW + c4 * 4) = v;
        }
    }
    __syncthreads();

    // ---- compute: warp = (head_local(3) x hh(2) x ww(4)), lane = t ----
    const int lane = tid & 31;
    const int warp = tid >> 5;
    const int hl   = warp >> 3;
    const int wp   = warp & 7;
    const int hhl  = wp >> 2;
    const int wwl  = wp & 3;

    const int prow = (hhl * 4 + wwl) * 32 + lane;
    const float* q0p = qs + prow * KROW + hl * 16;
    // q[t], q[t-1], q[t+1]. Lane 0's "t-1" / lane 31's "t+1" reads hit valid
    // (wrong-position) smem; their dots are shuffled off-warp or overridden
    // by the edge dot, never reaching an output.
    ull q0r[8], qmr[8], qpr[8];
    load8(q0r, q0p);
    load8(qmr, q0p - KROW);
    load8(qpr, q0p + KROW);

    const float* kcol0 = ks + ((hhl * 6 + wwl) * 34) * KROW + hl * 16;
    const float* rb    = rs + hl * 27;
    const bool  is_e0  = (lane == 0);
    const bool  is_e31 = (lane == 31);
    const int   erow   = is_e0 ? 0 : 33;       // halo row for edge dot

    float sum = 0.f, ax = 0.f, ay = 0.f, az = 0.f;

    #pragma unroll
    for (int cidx = 0; cidx < 9; ++cidx) {         // (i,j) column, compile-time
        const int i = cidx / 3, j = cidx % 3;
        const float* cb = kcol0 + ((i * 6 + j) * 34) * KROW;
        ull k8[8];
        load8(k8, cb + (lane + 1) * KROW);         // own t row

        const float pB = dot16(q0r, k8);           // dot(q[t],   k[t])
        const float pA = dot16(qmr, k8);           // dot(q[t-1], k[t])
        const float pC = dot16(qpr, k8);           // dot(q[t+1], k[t])

        float pE = 0.f;                            // edge lanes: halo dot
        if (is_e0 || is_e31) {
            ull e8[8];
            load8(e8, cb + erow * KROW);
            pE = dot16(q0r, e8);
        }

        float s_up = __shfl_down_sync(0xffffffffu, pA, 1);  // dot(q[t], k[t+1])
        float s_dn = __shfl_up_sync  (0xffffffffu, pC, 1);  // dot(q[t], k[t-1])
        if (is_e0)  s_dn = pE;
        if (is_e31) s_up = pE;

        const float e_dn = __expf(s_dn + rb[cidx * 3 + 0]);
        const float e_0  = __expf(pB   + rb[cidx * 3 + 1]);
        const float e_up = __expf(s_up + rb[cidx * 3 + 2]);
        const float es   = e_dn + e_0 + e_up;
        sum += es;
        if (i == 0) ax -= es; else if (i == 2) ax += es;
        if (j == 0) ay -= es; else if (j == 2) ay += es;
        az += e_up - e_dn;
    }

    const float inv = __fdividef(1.0f, sum);
    const int head = g * 3 + hl;
    long obase = ((((long)b * 18 + head * 3) * 64 + (h0 + hhl)) * 64 + (w0 + wwl)) * 64
               + t0 + lane;
    out[obase]              = ax * inv;
    out[obase + 262144]     = ay * inv;
    out[obase + 2 * 262144] = az * inv;
}

extern "C" void kernel_launch(void* const* d_in, const int* in_sizes, int n_in,
                              void* d_out, int out_size) {
    const float* q   = (const float*)d_in[0];
    const float* k   = (const float*)d_in[1];
    const float* rpb = (const float*)d_in[2];
    float* out = (float*)d_out;

    const int smem_bytes = (K_FLOATS + Q_FLOATS + 96) * sizeof(float); // 223360 B
    cudaFuncSetAttribute(natt3d_f32x2,
                         cudaFuncAttributeMaxDynamicSharedMemorySize, smem_bytes);
    natt3d_f32x2<<<4096, 768, smem_bytes>>>(q, k, rpb, out);
}

// round 16
// speedup vs baseline: 2.0815x; 1.1803x over previous
#include <cuda_runtime.h>
#include <cstdint>

// 3D neighborhood attention, B=2, H=W=T=64, C=96, NH=6, HD=16, KS=3 (27 window).
// Block = 2h x 4w x 32t positions, 3 heads (channel-split), 768 thr, ~218KB smem.
// R15 compute (warp-shuffle t-reuse + packed f32x2 dots) + NEW: tile fill via
// cp.async.cg 16B with hardware zero-fill for the halo (src-size=0). No LDG->STS
// register chains, MLP ~17 per thread, single wait_all + barrier.

#define KROW 52
#define K_ROWS (4 * 6 * 34)           // 816
#define K_FLOATS (K_ROWS * KROW)      // 42432
#define Q_FLOATS (256 * KROW)         // 13312

typedef unsigned long long ull;

__device__ __forceinline__ ull mul2(ull a, ull b) {
    ull d; asm("mul.rn.f32x2 %0, %1, %2;" : "=l"(d) : "l"(a), "l"(b)); return d;
}
__device__ __forceinline__ ull ffma2(ull a, ull b, ull c) {
    ull d; asm("fma.rn.f32x2 %0, %1, %2, %3;" : "=l"(d) : "l"(a), "l"(b), "l"(c));
    return d;
}
__device__ __forceinline__ float hadd2(ull v) {
    float lo, hi;
    asm("mov.b64 {%0,%1}, %2;" : "=f"(lo), "=f"(hi) : "l"(v));
    return lo + hi;
}
__device__ __forceinline__ float dot16(const ull* a, const ull* b) {
    ull acc = mul2(a[0], b[0]);
    acc = ffma2(a[1], b[1], acc); acc = ffma2(a[2], b[2], acc);
    acc = ffma2(a[3], b[3], acc); acc = ffma2(a[4], b[4], acc);
    acc = ffma2(a[5], b[5], acc); acc = ffma2(a[6], b[6], acc);
    acc = ffma2(a[7], b[7], acc);
    return hadd2(acc);
}
__device__ __forceinline__ void load8(ull* r, const float* p) {
    const ulonglong2* v = (const ulonglong2*)p;
    ulonglong2 v0 = v[0], v1 = v[1], v2 = v[2], v3 = v[3];
    r[0] = v0.x; r[1] = v0.y; r[2] = v1.x; r[3] = v1.y;
    r[4] = v2.x; r[5] = v2.y; r[6] = v3.x; r[7] = v3.y;
}
// 16B async copy; sbytes=0 -> smem slot zero-filled by HW (halo path).
__device__ __forceinline__ void cp16(uint32_t dst, const void* src, int sbytes) {
    asm volatile("cp.async.cg.shared.global [%0], [%1], 16, %2;"
                 :: "r"(dst), "l"(src), "r"(sbytes));
}

__global__ void __launch_bounds__(768, 1)
natt3d_cpasync(const float* __restrict__ q, const float* __restrict__ k,
               const float* __restrict__ rpb, float* __restrict__ out) {
    extern __shared__ float smem[];
    float* ks = smem;
    float* qs = smem + K_FLOATS;
    float* rs = qs + Q_FLOATS;

    const int tid = threadIdx.x;
    const int bx  = blockIdx.x;
    const int tt  = bx & 1;
    const int wt  = (bx >> 1) & 15;
    const int ht  = (bx >> 5) & 31;
    const int b   = (bx >> 10) & 1;
    const int g   = bx >> 11;             // head group: heads g*3..g*3+2
    const int w0  = wt * 4;
    const int h0  = ht * 2;
    const int t0  = tt * 32;
    const int cg  = g * 48;

    if (tid < 81) rs[tid] = __ldg(rpb + g * 81 + tid);

    const int bbase = b * (64 * 64 * 64 * 96);     // 25.2M < 2^31: 32-bit offsets
    const uint32_t ks_s = (uint32_t)__cvta_generic_to_shared(ks);
    const uint32_t qs_s = (uint32_t)__cvta_generic_to_shared(qs);

    // ---- fill k tile: 816 rows (4dh x 6dw x 34dt) x 12 x 16B, zero halo ----
    {
        const int c4 = tid % 12;
        int r = tid / 12;
        #pragma unroll
        for (int pass = 0; pass < 13; ++pass, r += 64) {
            if (r < 816) {
                const int dt = r % 34;
                const int rr = r / 34;            // dh*6 + dw
                const int ww = w0 - 1 + (rr % 6);
                const int hh = h0 - 1 + (rr / 6);
                const int t  = t0 - 1 + dt;
                const bool ok = (unsigned)hh < 64u && (unsigned)ww < 64u
                             && (unsigned)t < 64u;
                const float* src = k + bbase + ((hh * 64 + ww) * 64 + t) * 96
                                 + cg + c4 * 4;
                cp16(ks_s + (uint32_t)(r * (KROW * 4) + c4 * 16), src, ok ? 16 : 0);
            }
        }
    }

    // ---- fill q tile (raw; scale applied in prologue): 256 rows x 12 x 16B ----
    {
        const int c4 = tid % 12;
        int r = tid / 12;
        #pragma unroll
        for (int pass = 0; pass < 4; ++pass, r += 64) {
            const int tl = r & 31;
            const int ww = (r >> 5) & 3;
            const int hh = r >> 7;
            const float* src = q + bbase
                + (((h0 + hh) * 64 + w0 + ww) * 64 + t0 + tl) * 96 + cg + c4 * 4;
            cp16(qs_s + (uint32_t)(r * (KROW * 4) + c4 * 16), src, 16);
        }
    }
    asm volatile("cp.async.commit_group;");
    asm volatile("cp.async.wait_group 0;");
    __syncthreads();

    // ---- compute: warp = (head_local(3) x hh(2) x ww(4)), lane = t ----
    const int lane = tid & 31;
    const int warp = tid >> 5;
    const int hl   = warp >> 3;
    const int wp   = warp & 7;
    const int hhl  = wp >> 2;
    const int wwl  = wp & 3;

    const int prow = (hhl * 4 + wwl) * 32 + lane;
    const float* q0p = qs + prow * KROW + hl * 16;
    // q[t], q[t-1], q[t+1]. Lane 0's "t-1" / lane 31's "t+1" reads hit valid
    // (wrong-position) smem; their dots are shuffled off-warp or overridden
    // by the edge dot, never reaching an output.
    ull q0r[8], qmr[8], qpr[8];
    load8(q0r, q0p);
    load8(qmr, q0p - KROW);
    load8(qpr, q0p + KROW);
    const ull SC2 = 0x3e8000003e800000ULL;        // (0.25f, 0.25f)
    #pragma unroll
    for (int i = 0; i < 8; ++i) {
        q0r[i] = mul2(q0r[i], SC2);
        qmr[i] = mul2(qmr[i], SC2);
        qpr[i] = mul2(qpr[i], SC2);
    }

    const float* kcol0 = ks + ((hhl * 6 + wwl) * 34) * KROW + hl * 16;
    const float* rb    = rs + hl * 27;
    const bool  is_e0  = (lane == 0);
    const bool  is_e31 = (lane == 31);
    const int   erow   = is_e0 ? 0 : 33;          // halo row for edge dot

    float sum = 0.f, ax = 0.f, ay = 0.f, az = 0.f;

    #pragma unroll
    for (int cidx = 0; cidx < 9; ++cidx) {        // (i,j) column, compile-time
        const int i = cidx / 3, j = cidx % 3;
        const float* cb = kcol0 + ((i * 6 + j) * 34) * KROW;
        ull k8[8];
        load8(k8, cb + (lane + 1) * KROW);        // own t row

        const float pB = dot16(q0r, k8);          // dot(q[t],   k[t])
        const float pA = dot16(qmr, k8);          // dot(q[t-1], k[t])
        const float pC = dot16(qpr, k8);          // dot(q[t+1], k[t])

        float pE = 0.f;                           // edge lanes: halo dot
        if (is_e0 || is_e31) {
            ull e8[8];
            load8(e8, cb + erow * KROW);
            pE = dot16(q0r, e8);
        }

        float s_up = __shfl_down_sync(0xffffffffu, pA, 1);  // dot(q[t], k[t+1])
        float s_dn = __shfl_up_sync  (0xffffffffu, pC, 1);  // dot(q[t], k[t-1])
        if (is_e0)  s_dn = pE;
        if (is_e31) s_up = pE;

        const float e_dn = __expf(s_dn + rb[cidx * 3 + 0]);
        const float e_0  = __expf(pB   + rb[cidx * 3 + 1]);
        const float e_up = __expf(s_up + rb[cidx * 3 + 2]);
        const float es   = e_dn + e_0 + e_up;
        sum += es;
        if (i == 0) ax -= es; else if (i == 2) ax += es;
        if (j == 0) ay -= es; else if (j == 2) ay += es;
        az += e_up - e_dn;
    }

    const float inv = __fdividef(1.0f, sum);
    const int head = g * 3 + hl;
    long obase = ((((long)b * 18 + head * 3) * 64 + (h0 + hhl)) * 64 + (w0 + wwl)) * 64
               + t0 + lane;
    out[obase]              = ax * inv;
    out[obase + 262144]     = ay * inv;
    out[obase + 2 * 262144] = az * inv;
}

extern "C" void kernel_launch(void* const* d_in, const int* in_sizes, int n_in,
                              void* d_out, int out_size) {
    const float* q   = (const float*)d_in[0];
    const float* k   = (const float*)d_in[1];
    const float* rpb = (const float*)d_in[2];
    float* out = (float*)d_out;

    const int smem_bytes = (K_FLOATS + Q_FLOATS + 96) * sizeof(float); // 223360 B
    cudaFuncSetAttribute(natt3d_cpasync,
                         cudaFuncAttributeMaxDynamicSharedMemorySize, smem_bytes);
    natt3d_cpasync<<<4096, 768, smem_bytes>>>(q, k, rpb, out);
}